// round 1
// baseline (speedup 1.0000x reference)
#include <cuda_runtime.h>
#include <cstddef>

// PCLinearClassifierV2: the PC relaxation is algebraically a no-op (initial
// errors are exactly zero and remain zero), so the output is a plain 3-layer
// MLP forward pass:
//   h2  = relu(obs) @ W2^T + b2
//   h1  = relu(h2)  @ W1^T + b1
//   out = relu(h1)  @ W0^T + b0
//
// Fused SIMT fp32 GEMM: C[m,n] = b[n] + sum_k relu(A[m,k]) * W[n,k]
// BM=128, BN=64, BK=16, TM=TN=8, 128 threads, double-buffered smem.

namespace {
constexpr int BATCH = 1024;
constexpr int S0 = 1000;   // classes
constexpr int S1 = 2048;
constexpr int S2 = 1024;
constexpr int S3 = 4096;   // input

constexpr int BM = 128;
constexpr int BN = 64;
constexpr int BK = 16;
constexpr int TM = 8;
constexpr int TN = 8;
constexpr int NTHREADS = (BM / TM) * (BN / TN);  // 128
}

// Scratch activations (no allocation allowed in kernel_launch).
__device__ float g_h2[BATCH * S2];  // 4 MB
__device__ float g_h1[BATCH * S1];  // 8 MB

__global__ __launch_bounds__(NTHREADS)
void gemm_relu_bias(const float* __restrict__ A,   // M x K (relu applied on load)
                    const float* __restrict__ W,   // N x K
                    const float* __restrict__ bias,// N
                    float* __restrict__ C,         // M x N
                    int M, int N, int K)
{
    __shared__ float As[2][BK][BM + 4];
    __shared__ float Ws[2][BK][BN + 4];

    const int bm  = blockIdx.y * BM;
    const int bn  = blockIdx.x * BN;
    const int tid = threadIdx.x;

    // compute-tile coordinates
    const int tx = tid & 7;    // N direction: 8 groups of TN=8
    const int ty = tid >> 3;   // M direction: 16 groups of TM=8

    // loader coordinates (float4 granularity along K)
    const int lrow = tid >> 2;          // 0..31
    const int lcol = (tid & 3) << 2;    // 0,4,8,12

    float acc[TM][TN];
#pragma unroll
    for (int i = 0; i < TM; i++)
#pragma unroll
        for (int j = 0; j < TN; j++) acc[i][j] = 0.f;

    const int ntiles = K / BK;  // K is always a multiple of 16 here

    float4 ra[4];  // A: 4 rows per thread (lrow, lrow+32, lrow+64, lrow+96)
    float4 rw[2];  // W: 2 rows per thread (lrow, lrow+32)

    // ---- prologue: fetch tile 0 into registers ----
#pragma unroll
    for (int r = 0; r < 4; r++) {
        const int row = bm + lrow + r * 32;  // M is a multiple of BM: never OOB
        ra[r] = *reinterpret_cast<const float4*>(&A[(size_t)row * K + lcol]);
    }
#pragma unroll
    for (int r = 0; r < 2; r++) {
        const int row = bn + lrow + r * 32;
        rw[r] = (row < N)
            ? *reinterpret_cast<const float4*>(&W[(size_t)row * K + lcol])
            : make_float4(0.f, 0.f, 0.f, 0.f);
    }

    // store tile 0 into buffer 0 (relu fused on A)
#pragma unroll
    for (int r = 0; r < 4; r++) {
        const int m = lrow + r * 32;
        As[0][lcol + 0][m] = fmaxf(ra[r].x, 0.f);
        As[0][lcol + 1][m] = fmaxf(ra[r].y, 0.f);
        As[0][lcol + 2][m] = fmaxf(ra[r].z, 0.f);
        As[0][lcol + 3][m] = fmaxf(ra[r].w, 0.f);
    }
#pragma unroll
    for (int r = 0; r < 2; r++) {
        const int n = lrow + r * 32;
        Ws[0][lcol + 0][n] = rw[r].x;
        Ws[0][lcol + 1][n] = rw[r].y;
        Ws[0][lcol + 2][n] = rw[r].z;
        Ws[0][lcol + 3][n] = rw[r].w;
    }
    __syncthreads();

    int buf = 0;
    for (int t = 0; t < ntiles; t++) {
        // ---- prefetch next tile into registers (overlaps with compute) ----
        const bool have_next = (t + 1) < ntiles;
        if (have_next) {
            const int k0 = (t + 1) * BK;
#pragma unroll
            for (int r = 0; r < 4; r++) {
                const int row = bm + lrow + r * 32;
                ra[r] = *reinterpret_cast<const float4*>(&A[(size_t)row * K + k0 + lcol]);
            }
#pragma unroll
            for (int r = 0; r < 2; r++) {
                const int row = bn + lrow + r * 32;
                rw[r] = (row < N)
                    ? *reinterpret_cast<const float4*>(&W[(size_t)row * K + k0 + lcol])
                    : make_float4(0.f, 0.f, 0.f, 0.f);
            }
        }

        // ---- compute on current buffer ----
#pragma unroll
        for (int k = 0; k < BK; k++) {
            float a_[TM], w_[TN];
#pragma unroll
            for (int i = 0; i < TM; i++) a_[i] = As[buf][k][ty * TM + i];
#pragma unroll
            for (int j = 0; j < TN; j++) w_[j] = Ws[buf][k][tx * TN + j];
#pragma unroll
            for (int i = 0; i < TM; i++)
#pragma unroll
                for (int j = 0; j < TN; j++)
                    acc[i][j] = fmaf(a_[i], w_[j], acc[i][j]);
        }

        // ---- commit prefetched tile to the other buffer ----
        if (have_next) {
            const int nb = buf ^ 1;
#pragma unroll
            for (int r = 0; r < 4; r++) {
                const int m = lrow + r * 32;
                As[nb][lcol + 0][m] = fmaxf(ra[r].x, 0.f);
                As[nb][lcol + 1][m] = fmaxf(ra[r].y, 0.f);
                As[nb][lcol + 2][m] = fmaxf(ra[r].z, 0.f);
                As[nb][lcol + 3][m] = fmaxf(ra[r].w, 0.f);
            }
#pragma unroll
            for (int r = 0; r < 2; r++) {
                const int n = lrow + r * 32;
                Ws[nb][lcol + 0][n] = rw[r].x;
                Ws[nb][lcol + 1][n] = rw[r].y;
                Ws[nb][lcol + 2][n] = rw[r].z;
                Ws[nb][lcol + 3][n] = rw[r].w;
            }
        }
        __syncthreads();
        buf ^= 1;
    }

    // ---- epilogue: bias add + store (guard N for the 1000-class layer) ----
#pragma unroll
    for (int j = 0; j < TN; j++) {
        const int col = bn + tx * TN + j;
        if (col < N) {
            const float bv = bias[col];
#pragma unroll
            for (int i = 0; i < TM; i++) {
                const int row = bm + ty * TM + i;
                C[(size_t)row * N + col] = acc[i][j] + bv;
            }
        }
    }
}

extern "C" void kernel_launch(void* const* d_in, const int* in_sizes, int n_in,
                              void* d_out, int out_size)
{
    const float* obs = (const float*)d_in[0];  // (1024, 4096)
    const float* W0  = (const float*)d_in[1];  // (1000, 2048)
    const float* b0  = (const float*)d_in[2];  // (1000,)
    const float* W1  = (const float*)d_in[3];  // (2048, 1024)
    const float* b1  = (const float*)d_in[4];  // (2048,)
    const float* W2  = (const float*)d_in[5];  // (1024, 4096)
    const float* b2  = (const float*)d_in[6];  // (1024,)
    float* out = (float*)d_out;                // (1024, 1000)

    float* h2 = nullptr;
    float* h1 = nullptr;
    cudaGetSymbolAddress((void**)&h2, g_h2);   // capture-safe: no stream op, no alloc
    cudaGetSymbolAddress((void**)&h1, g_h1);

    dim3 block(NTHREADS);

    // h2 = relu(obs) @ W2^T + b2   : M=1024, N=1024, K=4096  -> 16x8 = 128 CTAs
    gemm_relu_bias<<<dim3(S2 / BN, BATCH / BM), block>>>(obs, W2, b2, h2, BATCH, S2, S3);
    // h1 = relu(h2) @ W1^T + b1    : M=1024, N=2048, K=1024  -> 32x8 = 256 CTAs
    gemm_relu_bias<<<dim3(S1 / BN, BATCH / BM), block>>>(h2, W1, b1, h1, BATCH, S1, S2);
    // out = relu(h1) @ W0^T + b0   : M=1024, N=1000, K=2048  -> 16x8 = 128 CTAs
    gemm_relu_bias<<<dim3((S0 + BN - 1) / BN, BATCH / BM), block>>>(h1, W0, b0, out, BATCH, S0, S1);
}

// round 5
// speedup vs baseline: 2.7925x; 2.7925x over previous
#include <cuda_runtime.h>
#include <cuda_bf16.h>
#include <cstdint>
#include <cstddef>

// PCLinearClassifierV2: PC relaxation is algebraically identity (initial
// errors are exactly zero and stay zero), so output = 3-layer MLP forward:
//   h2 = relu(obs) @ W2^T + b2 ; h1 = relu(h2) @ W1^T + b1 ; out = relu(h1) @ W0^T + b0
//
// bf16 split-precision (hi/lo, 3 products) GEMM on mma.sync.m16n8k16
// (portable PTX: harness compiles at virtual arch compute_100 -> no tcgen05).
// fp32 register accumulators. BM=128, BN=64, BK=64, 256 thr,
// 2-stage cp.async pipeline (108 KB smem), pitch-72 conflict-free ldmatrix.

#define S0 1000
#define S1 2048
#define S2 1024
#define S3 4096
#define BATCH 1024

#define BM 128
#define BN 64
#define BK 64
#define NTHR 256
#define NS 2

#define PITCHB 144u                     // bytes per smem row (72 bf16)
#define A_HI 0u
#define A_LO (128u * PITCHB)            // 18432
#define W_HI (2u * 128u * PITCHB)       // 36864
#define W_LO (W_HI + 64u * PITCHB)      // 46080
#define STAGE (W_LO + 64u * PITCHB)     // 55296
#define SMEM_BYTES (NS * STAGE)         // 110592

// ---------------- scratch (bf16 hi/lo copies + hidden activations) ----------
__device__ __align__(256) __nv_bfloat16 g_obs_hi[BATCH*S3], g_obs_lo[BATCH*S3];
__device__ __align__(256) __nv_bfloat16 g_W2_hi [S2*S3],    g_W2_lo [S2*S3];
__device__ __align__(256) __nv_bfloat16 g_W1_hi [S1*S2],    g_W1_lo [S1*S2];
__device__ __align__(256) __nv_bfloat16 g_W0_hi [S0*S1],    g_W0_lo [S0*S1];
__device__ __align__(256) __nv_bfloat16 g_h2_hi [BATCH*S2], g_h2_lo [BATCH*S2];
__device__ __align__(256) __nv_bfloat16 g_h1_hi [BATCH*S1], g_h1_lo [BATCH*S1];

// ---------------- fp32 -> bf16 hi/lo split (optionally with relu) -----------
__global__ void split_kernel(const float4* __restrict__ src,
                             __nv_bfloat162* __restrict__ hi,
                             __nv_bfloat162* __restrict__ lo,
                             int n4, int do_relu)
{
    int i = blockIdx.x * blockDim.x + threadIdx.x;
    if (i >= n4) return;
    float4 v = src[i];
    if (do_relu) {
        v.x = fmaxf(v.x, 0.f); v.y = fmaxf(v.y, 0.f);
        v.z = fmaxf(v.z, 0.f); v.w = fmaxf(v.w, 0.f);
    }
    float a[4] = {v.x, v.y, v.z, v.w};
    __nv_bfloat16 h[4], l[4];
#pragma unroll
    for (int e = 0; e < 4; e++) {
        h[e] = __float2bfloat16(a[e]);
        l[e] = __float2bfloat16(a[e] - __bfloat162float(h[e]));
    }
    hi[2*i+0] = __halves2bfloat162(h[0], h[1]);
    hi[2*i+1] = __halves2bfloat162(h[2], h[3]);
    lo[2*i+0] = __halves2bfloat162(l[0], l[1]);
    lo[2*i+1] = __halves2bfloat162(l[2], l[3]);
}

// ---------------- PTX helpers -----------------------------------------------
__device__ __forceinline__ uint32_t smem_u32(const void* p) {
    uint32_t a;
    asm("{ .reg .u64 t; cvta.to.shared.u64 t, %1; cvt.u32.u64 %0, t; }" : "=r"(a) : "l"(p));
    return a;
}

__device__ __forceinline__ void cp16(uint32_t dst, const void* src, bool valid) {
    asm volatile("cp.async.cg.shared.global [%0], [%1], 16, %2;"
                 :: "r"(dst), "l"(src), "r"(valid ? 16u : 0u));
}

__device__ __forceinline__ void ldm_x4(uint32_t* r, uint32_t addr) {
    asm volatile("ldmatrix.sync.aligned.m8n8.x4.shared.b16 {%0,%1,%2,%3}, [%4];"
                 : "=r"(r[0]), "=r"(r[1]), "=r"(r[2]), "=r"(r[3]) : "r"(addr));
}

__device__ __forceinline__ void mma16816(float* c, const uint32_t* a,
                                         uint32_t b0, uint32_t b1) {
    asm volatile(
        "mma.sync.aligned.m16n8k16.row.col.f32.bf16.bf16.f32 "
        "{%0,%1,%2,%3}, {%4,%5,%6,%7}, {%8,%9}, {%0,%1,%2,%3};"
        : "+f"(c[0]), "+f"(c[1]), "+f"(c[2]), "+f"(c[3])
        : "r"(a[0]), "r"(a[1]), "r"(a[2]), "r"(a[3]), "r"(b0), "r"(b1));
}

// ---------------- fused GEMM ------------------------------------------------
// mode 0: out = relu(D + bias) -> bf16 hi/lo ; mode 1: out = D + bias -> fp32
__global__ __launch_bounds__(NTHR, 1)
void gemm_mma(const __nv_bfloat16* __restrict__ Ahi, const __nv_bfloat16* __restrict__ Alo,
              const __nv_bfloat16* __restrict__ Whi, const __nv_bfloat16* __restrict__ Wlo,
              const float* __restrict__ bias,
              float* __restrict__ outF,
              __nv_bfloat16* __restrict__ outHi, __nv_bfloat16* __restrict__ outLo,
              int N, int K, int mode)
{
    extern __shared__ char smem[];
    const uint32_t sbase = smem_u32(smem);
    const int tid  = threadIdx.x;
    const int lane = tid & 31;
    const int wid  = tid >> 5;
    const int wm   = wid >> 1;      // 0..3 (M)
    const int wn   = wid & 1;       // 0..1 (N)
    const int bm   = blockIdx.y * BM;
    const int bn   = blockIdx.x * BN;
    const int T    = K / BK;

    float acc[2][4][4];
#pragma unroll
    for (int mt = 0; mt < 2; mt++)
#pragma unroll
        for (int nt = 0; nt < 4; nt++)
#pragma unroll
            for (int e = 0; e < 4; e++) acc[mt][nt][e] = 0.f;

    // -------- stage loader: 12 cp.async of 16B per thread + commit --------
    auto load_stage = [&](int t) {
        const uint32_t sb = sbase + (uint32_t)(t & 1) * STAGE;
        const size_t k0 = (size_t)t * BK;
#pragma unroll
        for (int i = 0; i < 4; i++) {            // A: 128 rows x 8 chunks
            int idx = tid + i * NTHR;
            int row = idx >> 3, ch = idx & 7;
            uint32_t d = sb + (uint32_t)row * PITCHB + (uint32_t)ch * 16u;
            size_t go = (size_t)(bm + row) * (size_t)K + k0 + (size_t)(ch << 3);
            cp16(d + A_HI, Ahi + go, true);
            cp16(d + A_LO, Alo + go, true);
        }
#pragma unroll
        for (int i = 0; i < 2; i++) {            // W: 64 rows x 8 chunks
            int idx = tid + i * NTHR;
            int row = idx >> 3, ch = idx & 7;
            bool v = (bn + row) < N;
            int rs = v ? (bn + row) : 0;
            uint32_t d = sb + (uint32_t)row * PITCHB + (uint32_t)ch * 16u;
            size_t go = (size_t)rs * (size_t)K + k0 + (size_t)(ch << 3);
            cp16(d + W_HI, Whi + go, v);
            cp16(d + W_LO, Wlo + go, v);
        }
        asm volatile("cp.async.commit_group;" ::: "memory");
    };

    load_stage(0);
    load_stage(1);

    const int arow = wm * 32 + (lane & 15);
    const int brow = wn * 32 + (lane & 15);
    const int koff = (lane >> 4) << 3;           // 0 or 8

    for (int t = 0; t < T; t++) {
        asm volatile("cp.async.wait_group 1;" ::: "memory");
        __syncthreads();                         // stage t visible to all

        const uint32_t sb = sbase + (uint32_t)(t & 1) * STAGE;
#pragma unroll
        for (int ks = 0; ks < 4; ks++) {
            const uint32_t kb = (uint32_t)(ks * 16 + koff) * 2u;
            uint32_t ah[2][4], al[2][4], bh[2][4], bl[2][4];
#pragma unroll
            for (int mt = 0; mt < 2; mt++) {
                uint32_t ad = sb + (uint32_t)(arow + mt * 16) * PITCHB + kb;
                ldm_x4(ah[mt], ad + A_HI);
                ldm_x4(al[mt], ad + A_LO);
            }
#pragma unroll
            for (int g = 0; g < 2; g++) {
                uint32_t bd = sb + (uint32_t)(brow + g * 16) * PITCHB + kb;
                ldm_x4(bh[g], bd + W_HI);
                ldm_x4(bl[g], bd + W_LO);
            }
#pragma unroll
            for (int mt = 0; mt < 2; mt++)
#pragma unroll
                for (int nt = 0; nt < 4; nt++) {
                    const int g = nt >> 1, s = nt & 1;
                    mma16816(acc[mt][nt], ah[mt], bh[g][s], bh[g][s + 2]);
                    mma16816(acc[mt][nt], ah[mt], bl[g][s], bl[g][s + 2]);
                    mma16816(acc[mt][nt], al[mt], bh[g][s], bh[g][s + 2]);
                }
        }

        __syncthreads();                         // all reads of buf t&1 done
        if (t + 2 < T) load_stage(t + 2);        // overwrite buf t&1
        else asm volatile("cp.async.commit_group;" ::: "memory");
    }

    // -------- epilogue: bias (+relu+split) from registers --------
    const int row0 = bm + wm * 32 + (lane >> 2);
    const int col0 = bn + wn * 32 + (lane & 3) * 2;
#pragma unroll
    for (int mt = 0; mt < 2; mt++) {
#pragma unroll
        for (int nt = 0; nt < 4; nt++) {
            const int c = col0 + nt * 8;
#pragma unroll
            for (int h = 0; h < 2; h++) {
                const int r = row0 + mt * 16 + h * 8;
                float v0 = acc[mt][nt][2 * h + 0];
                float v1 = acc[mt][nt][2 * h + 1];
                if (mode == 0) {
                    v0 = fmaxf(v0 + bias[c], 0.f);
                    v1 = fmaxf(v1 + bias[c + 1], 0.f);
                    __nv_bfloat16 h0 = __float2bfloat16(v0);
                    __nv_bfloat16 h1 = __float2bfloat16(v1);
                    __nv_bfloat16 l0 = __float2bfloat16(v0 - __bfloat162float(h0));
                    __nv_bfloat16 l1 = __float2bfloat16(v1 - __bfloat162float(h1));
                    size_t o = (size_t)r * (size_t)N + (size_t)c;
                    *(__nv_bfloat162*)(outHi + o) = __halves2bfloat162(h0, h1);
                    *(__nv_bfloat162*)(outLo + o) = __halves2bfloat162(l0, l1);
                } else if (c < N) {
                    float2 v = make_float2(v0 + bias[c], v1 + bias[c + 1]);
                    *(float2*)(outF + (size_t)r * (size_t)N + (size_t)c) = v;
                }
            }
        }
    }
}

// ---------------- launch ----------------------------------------------------
extern "C" void kernel_launch(void* const* d_in, const int* in_sizes, int n_in,
                              void* d_out, int out_size)
{
    const float* obs = (const float*)d_in[0];  // (1024, 4096)
    const float* W0  = (const float*)d_in[1];  // (1000, 2048)
    const float* b0  = (const float*)d_in[2];
    const float* W1  = (const float*)d_in[3];  // (2048, 1024)
    const float* b1  = (const float*)d_in[4];
    const float* W2  = (const float*)d_in[5];  // (1024, 4096)
    const float* b2  = (const float*)d_in[6];
    float* out = (float*)d_out;                // (1024, 1000)

    __nv_bfloat16 *obs_hi, *obs_lo, *W2hi, *W2lo, *W1hi, *W1lo, *W0hi, *W0lo;
    __nv_bfloat16 *h2hi, *h2lo, *h1hi, *h1lo;
    cudaGetSymbolAddress((void**)&obs_hi, g_obs_hi);
    cudaGetSymbolAddress((void**)&obs_lo, g_obs_lo);
    cudaGetSymbolAddress((void**)&W2hi,  g_W2_hi);
    cudaGetSymbolAddress((void**)&W2lo,  g_W2_lo);
    cudaGetSymbolAddress((void**)&W1hi,  g_W1_hi);
    cudaGetSymbolAddress((void**)&W1lo,  g_W1_lo);
    cudaGetSymbolAddress((void**)&W0hi,  g_W0_hi);
    cudaGetSymbolAddress((void**)&W0lo,  g_W0_lo);
    cudaGetSymbolAddress((void**)&h2hi,  g_h2_hi);
    cudaGetSymbolAddress((void**)&h2lo,  g_h2_lo);
    cudaGetSymbolAddress((void**)&h1hi,  g_h1_hi);
    cudaGetSymbolAddress((void**)&h1lo,  g_h1_lo);

    cudaFuncSetAttribute(gemm_mma, cudaFuncAttributeMaxDynamicSharedMemorySize, SMEM_BYTES);

    {   // bf16 hi/lo splits (relu fused into obs split)
        int n4;
        n4 = BATCH*S3/4; split_kernel<<<(n4+255)/256, 256>>>((const float4*)obs,
             (__nv_bfloat162*)obs_hi, (__nv_bfloat162*)obs_lo, n4, 1);
        n4 = S2*S3/4;    split_kernel<<<(n4+255)/256, 256>>>((const float4*)W2,
             (__nv_bfloat162*)W2hi, (__nv_bfloat162*)W2lo, n4, 0);
        n4 = S1*S2/4;    split_kernel<<<(n4+255)/256, 256>>>((const float4*)W1,
             (__nv_bfloat162*)W1hi, (__nv_bfloat162*)W1lo, n4, 0);
        n4 = S0*S1/4;    split_kernel<<<(n4+255)/256, 256>>>((const float4*)W0,
             (__nv_bfloat162*)W0hi, (__nv_bfloat162*)W0lo, n4, 0);
    }

    dim3 blk(NTHR);
    // h2 = relu(obs) @ W2^T + b2 : N=1024, K=4096 -> 16x8 = 128 CTAs
    gemm_mma<<<dim3(S2/BN, BATCH/BM), blk, SMEM_BYTES>>>(
        obs_hi, obs_lo, W2hi, W2lo, b2, nullptr, h2hi, h2lo, S2, S3, 0);
    // h1 = relu(h2) @ W1^T + b1 : N=2048, K=1024 -> 32x8 = 256 CTAs
    gemm_mma<<<dim3(S1/BN, BATCH/BM), blk, SMEM_BYTES>>>(
        h2hi, h2lo, W1hi, W1lo, b1, nullptr, h1hi, h1lo, S1, S2, 0);
    // out = relu(h1) @ W0^T + b0 : N=1000, K=2048 -> 16x8 = 128 CTAs
    gemm_mma<<<dim3((S0 + BN - 1)/BN, BATCH/BM), blk, SMEM_BYTES>>>(
        h1hi, h1lo, W0hi, W0lo, b0, out, nullptr, nullptr, S0, S1, 1);
}